// round 9
// baseline (speedup 1.0000x reference)
#include <cuda_runtime.h>

// Problem constants
constexpr int Nn = 4096;   // nodes
constexpr int Dd = 256;    // model dim
constexpr int Ee = 65536;  // edges
constexpr int DCAP = 64;   // per-row bucket capacity (Poisson(16): P(deg>64) ~ 1e-19)

constexpr int BK   = 32;   // GEMM k-tile
constexpr int KPAD = 36;   // padded smem row: banks (36r+c)&31=(4r+c)&31 all distinct

constexpr int SMEM_T_ELEMS = 64 * KPAD;    // one 64x32 tile buffer (padded)

// ---------------------------------------------------------------------------
// Scratch
// ---------------------------------------------------------------------------
__device__ float    g_Q[Nn * Dd];
__device__ float    g_K[Nn * Dd];
__device__ float    g_V[Nn * Dd];
__device__ float    g_attn[Nn * Dd];
__device__ float    g_vsum[Dd];
__device__ int      g_cnt[Nn];            // per-row edge count
__device__ int      g_adj[Nn * DCAP];     // fixed-stride row buckets
// tf32-rounded operands
__device__ float    g_xr[Nn * Dd];
__device__ float    g_Wqr[Dd * Dd];
__device__ float    g_Wkr[Dd * Dd];
__device__ float    g_Wvr[Dd * Dd];
__device__ float    g_Wor[Dd * Dd];

// ---------------------------------------------------------------------------
__device__ __forceinline__ float tf32_rna(float f) {
    unsigned u;
    asm("cvt.rna.tf32.f32 %0, %1;" : "=r"(u) : "f"(f));
    return __uint_as_float(u);
}

__global__ void zero_small_kernel() {
    int idx = blockIdx.x * blockDim.x + threadIdx.x;
    if (idx < Nn) g_cnt[idx] = 0;
    if (idx < Dd) g_vsum[idx] = 0.0f;
}

// Single-pass bucketing: no hist/scan/scatter chain.
__global__ void bucket_kernel(const int* __restrict__ ei) {
    int e = blockIdx.x * blockDim.x + threadIdx.x;
    if (e >= Ee) return;
    int row = ei[e] & (Nn - 1);
    int col = ei[Ee + e] & (Nn - 1);
    int p = atomicAdd(&g_cnt[row], 1);
    if (p < DCAP) g_adj[row * DCAP + p] = col;
}

// ---------------------------------------------------------------------------
// tf32 rounding pre-pass
// ---------------------------------------------------------------------------
__global__ void round_kernel(const float* __restrict__ x,
                             const float* __restrict__ Wq,
                             const float* __restrict__ Wk,
                             const float* __restrict__ Wv,
                             const float* __restrict__ Wo) {
    int idx = blockIdx.x * blockDim.x + threadIdx.x;
    int stride = gridDim.x * blockDim.x;
    for (int i = idx; i < Nn * Dd; i += stride) g_xr[i] = tf32_rna(x[i]);
    for (int i = idx; i < Dd * Dd; i += stride) {
        g_Wqr[i] = tf32_rna(Wq[i]);
        g_Wkr[i] = tf32_rna(Wk[i]);
        g_Wvr[i] = tf32_rna(Wv[i]);
        g_Wor[i] = tf32_rna(Wo[i]);
    }
}

// ---------------------------------------------------------------------------
// TF32 tensor-core GEMM: C[M,256] = A[M,256] @ W[256,256]^T (+ optional bias)
// BM=64, BN=64, BK=32; 128 threads = 4 warps (2m x 2n), warp tile 32x32.
// Grid-limited occupancy fix: QKV grid = 768 CTAs (5.2/SM), smem 36.9 KB
// (static, 6 CTAs/SM capacity) -> ~21 resident warps/SM.
// ---------------------------------------------------------------------------
__device__ __forceinline__ unsigned smem_u32(const void* p) {
    return (unsigned)__cvta_generic_to_shared(p);
}
__device__ __forceinline__ void cp_async16(unsigned dst, const void* src) {
    asm volatile("cp.async.cg.shared.global [%0], [%1], 16;" :: "r"(dst), "l"(src));
}
__device__ __forceinline__ void cp_commit() {
    asm volatile("cp.async.commit_group;" ::: "memory");
}
template <int N> __device__ __forceinline__ void cp_wait() {
    asm volatile("cp.async.wait_group %0;" :: "n"(N) : "memory");
}

__device__ __forceinline__ void mma_tf32(float* d, float a0, float a1, float a2, float a3,
                                         float b0, float b1) {
    asm volatile(
        "mma.sync.aligned.m16n8k8.row.col.f32.tf32.tf32.f32 "
        "{%0,%1,%2,%3}, {%4,%5,%6,%7}, {%8,%9}, {%0,%1,%2,%3};\n"
        : "+f"(d[0]), "+f"(d[1]), "+f"(d[2]), "+f"(d[3])
        : "r"(__float_as_uint(a0)), "r"(__float_as_uint(a1)),
          "r"(__float_as_uint(a2)), "r"(__float_as_uint(a3)),
          "r"(__float_as_uint(b0)), "r"(__float_as_uint(b1)));
}

__device__ __forceinline__ void gemm_body(const float* __restrict__ A,
                                          const float* __restrict__ W,
                                          const float* __restrict__ bias,
                                          float* __restrict__ C) {
    __shared__ __align__(16) float As[2][SMEM_T_ELEMS];
    __shared__ __align__(16) float Ws[2][SMEM_T_ELEMS];

    const int tid  = threadIdx.x;
    const int lane = tid & 31;
    const int wid  = tid >> 5;          // 0..3
    const int wm0  = (wid & 1) * 32;    // warp m-offset
    const int wn0  = (wid >> 1) * 32;   // warp n-offset
    const int m0   = blockIdx.y * 64;
    const int n0   = blockIdx.x * 64;

    const int r = lane >> 2;   // 0..7
    const int c = lane & 3;    // 0..3

    // Staging: each thread copies 16 consecutive floats of one row (A and W)
    const int rr  = tid >> 1;          // 0..63
    const int kk0 = (tid & 1) * 16;    // 0 or 16

    float d[2][4][4];
#pragma unroll
    for (int i = 0; i < 2; i++)
#pragma unroll
        for (int j = 0; j < 4; j++)
#pragma unroll
            for (int q = 0; q < 4; q++) d[i][j][q] = 0.0f;

    auto do_stage = [&](int s, int t) {
        unsigned a_dst = smem_u32(&As[s][rr * KPAD + kk0]);
        const float* a_src = &A[(size_t)(m0 + rr) * Dd + t * BK + kk0];
        cp_async16(a_dst,      a_src);
        cp_async16(a_dst + 16, a_src + 4);
        cp_async16(a_dst + 32, a_src + 8);
        cp_async16(a_dst + 48, a_src + 12);
        unsigned w_dst = smem_u32(&Ws[s][rr * KPAD + kk0]);
        const float* w_src = &W[(size_t)(n0 + rr) * Dd + t * BK + kk0];
        cp_async16(w_dst,      w_src);
        cp_async16(w_dst + 16, w_src + 4);
        cp_async16(w_dst + 32, w_src + 8);
        cp_async16(w_dst + 48, w_src + 12);
        cp_commit();
    };

    do_stage(0, 0);

    constexpr int NT = Dd / BK;  // 8 tiles
    for (int t = 0; t < NT; t++) {
        if (t + 1 < NT) { do_stage((t + 1) & 1, t + 1); cp_wait<1>(); }
        else            { cp_wait<0>(); }
        __syncthreads();
        const int s = t & 1;

#pragma unroll
        for (int kk = 0; kk < BK; kk += 8) {
            float a[2][4], b[4][2];
#pragma unroll
            for (int i = 0; i < 2; i++) {
                const float* p = &As[s][(wm0 + 16 * i + r) * KPAD + kk + c];
                a[i][0] = p[0];
                a[i][1] = p[8 * KPAD];
                a[i][2] = p[4];
                a[i][3] = p[8 * KPAD + 4];
            }
#pragma unroll
            for (int j = 0; j < 4; j++) {
                const float* p = &Ws[s][(wn0 + 8 * j + r) * KPAD + kk + c];
                b[j][0] = p[0];
                b[j][1] = p[4];
            }
#pragma unroll
            for (int i = 0; i < 2; i++)
#pragma unroll
                for (int j = 0; j < 4; j++)
                    mma_tf32(d[i][j], a[i][0], a[i][1], a[i][2], a[i][3],
                             b[j][0], b[j][1]);
        }
        __syncthreads();
    }

#pragma unroll
    for (int i = 0; i < 2; i++) {
#pragma unroll
        for (int j = 0; j < 4; j++) {
            int m = m0 + wm0 + 16 * i + r;
            int n = n0 + wn0 + 8 * j + 2 * c;
            float2 v0 = make_float2(d[i][j][0], d[i][j][1]);
            float2 v1 = make_float2(d[i][j][2], d[i][j][3]);
            if (bias) {
                float bx = bias[n], by = bias[n + 1];
                v0.x += bx; v0.y += by;
                v1.x += bx; v1.y += by;
            }
            *(float2*)&C[(size_t)m * Dd + n] = v0;
            *(float2*)&C[(size_t)(m + 8) * Dd + n] = v1;
        }
    }
}

__global__ __launch_bounds__(128, 6) void gemm_qkv_kernel() {
    const float* W = (blockIdx.z == 0) ? g_Wqr : (blockIdx.z == 1) ? g_Wkr : g_Wvr;
    float* C = (blockIdx.z == 0) ? g_Q : (blockIdx.z == 1) ? g_K : g_V;
    gemm_body(g_xr, W, nullptr, C);
}

__global__ __launch_bounds__(128, 6) void gemm_out_kernel(const float* __restrict__ bo,
                                                          float* __restrict__ out) {
    gemm_body(g_attn, g_Wor, bo, out);
}

// ---------------------------------------------------------------------------
// Column sums of V
// ---------------------------------------------------------------------------
__global__ void vsum_kernel() {
    int c = threadIdx.x;
    int r0 = blockIdx.x * 16;
    float s = 0.0f;
#pragma unroll
    for (int r = 0; r < 16; r++) s += g_V[(size_t)(r0 + r) * Dd + c];
    atomicAdd(&g_vsum[c], s);
}

// ---------------------------------------------------------------------------
// Row kernel: one WARP per row (unchanged from R6 winner).
// ---------------------------------------------------------------------------
__device__ __forceinline__ void edge_accum(int col, int lane, const float* q,
                                           float* acc, float& dn) {
    const float* kp = g_K + (size_t)col * Dd + lane * 8;
    const float* vp = g_V + (size_t)col * Dd + lane * 8;
    float4 k1 = *(const float4*)kp;
    float4 k2 = *(const float4*)(kp + 4);
    float4 v1 = *(const float4*)vp;
    float4 v2 = *(const float4*)(vp + 4);
    float s = q[0] * k1.x + q[1] * k1.y + q[2] * k1.z + q[3] * k1.w
            + q[4] * k2.x + q[5] * k2.y + q[6] * k2.z + q[7] * k2.w;
    s += __shfl_xor_sync(0xffffffffu, s, 1);
    s += __shfl_xor_sync(0xffffffffu, s, 2);
    const float inv_scale = 0.17677669529663687f;  // 1/sqrt(32)
    float w = __expf(s * inv_scale) - 1.0f;
    acc[0] += w * v1.x; acc[1] += w * v1.y; acc[2] += w * v1.z; acc[3] += w * v1.w;
    acc[4] += w * v2.x; acc[5] += w * v2.y; acc[6] += w * v2.z; acc[7] += w * v2.w;
    dn += w;
}

__global__ __launch_bounds__(256) void row_kernel() {
    const int lane = threadIdx.x & 31;
    const int row  = blockIdx.x * 8 + (threadIdx.x >> 5);

    const int deg = min(g_cnt[row], DCAP);
    const int* adj = g_adj + row * DCAP;

    int col0 = (lane < deg)      ? adj[lane]      : (-1 - lane);
    int col1 = (32 + lane < deg) ? adj[32 + lane] : (-1 - lane);

    unsigned m0 = __match_any_sync(0xffffffffu, col0);
    bool keep0 = (lane < deg) && (lane == __ffs(m0) - 1);
    unsigned bm0 = __ballot_sync(0xffffffffu, keep0);

    unsigned bm1 = 0u;
    if (deg > 32) {
        unsigned m1 = __match_any_sync(0xffffffffu, col1);
        bool keep1 = (32 + lane < deg) && (lane == __ffs(m1) - 1);
        for (int j = 0; j < 32; j++) {
            int cj = __shfl_sync(0xffffffffu, col0, j);
            if (j < deg && cj == col1) keep1 = false;
        }
        bm1 = __ballot_sync(0xffffffffu, keep1);
    }

    float q[8];
    {
        const float* qp = g_Q + (size_t)row * Dd + lane * 8;
        float4 a = *(const float4*)qp;
        float4 b = *(const float4*)(qp + 4);
        q[0] = a.x; q[1] = a.y; q[2] = a.z; q[3] = a.w;
        q[4] = b.x; q[5] = b.y; q[6] = b.z; q[7] = b.w;
    }

    float acc[8] = {0, 0, 0, 0, 0, 0, 0, 0};
    float dn = 0.0f;

#pragma unroll 1
    for (int ch = 0; ch < 2; ch++) {
        unsigned bm = (ch == 0) ? bm0 : bm1;
        int cols = (ch == 0) ? col0 : col1;
        while (bm) {
            int b0 = __ffs(bm) - 1; bm &= bm - 1;
            int cA = __shfl_sync(0xffffffffu, cols, b0);
            if (bm) {
                int b1 = __ffs(bm) - 1; bm &= bm - 1;
                int cB = __shfl_sync(0xffffffffu, cols, b1);
                const float* kA = g_K + (size_t)cA * Dd + lane * 8;
                const float* vA = g_V + (size_t)cA * Dd + lane * 8;
                const float* kB = g_K + (size_t)cB * Dd + lane * 8;
                const float* vB = g_V + (size_t)cB * Dd + lane * 8;
                float4 kA1 = *(const float4*)kA, kA2 = *(const float4*)(kA + 4);
                float4 vA1 = *(const float4*)vA, vA2 = *(const float4*)(vA + 4);
                float4 kB1 = *(const float4*)kB, kB2 = *(const float4*)(kB + 4);
                float4 vB1 = *(const float4*)vB, vB2 = *(const float4*)(vB + 4);

                float sA = q[0]*kA1.x + q[1]*kA1.y + q[2]*kA1.z + q[3]*kA1.w
                         + q[4]*kA2.x + q[5]*kA2.y + q[6]*kA2.z + q[7]*kA2.w;
                float sB = q[0]*kB1.x + q[1]*kB1.y + q[2]*kB1.z + q[3]*kB1.w
                         + q[4]*kB2.x + q[5]*kB2.y + q[6]*kB2.z + q[7]*kB2.w;
                sA += __shfl_xor_sync(0xffffffffu, sA, 1);
                sB += __shfl_xor_sync(0xffffffffu, sB, 1);
                sA += __shfl_xor_sync(0xffffffffu, sA, 2);
                sB += __shfl_xor_sync(0xffffffffu, sB, 2);
                const float inv_scale = 0.17677669529663687f;
                float wA = __expf(sA * inv_scale) - 1.0f;
                float wB = __expf(sB * inv_scale) - 1.0f;
                acc[0] += wA*vA1.x + wB*vB1.x; acc[1] += wA*vA1.y + wB*vB1.y;
                acc[2] += wA*vA1.z + wB*vB1.z; acc[3] += wA*vA1.w + wB*vB1.w;
                acc[4] += wA*vA2.x + wB*vB2.x; acc[5] += wA*vA2.y + wB*vB2.y;
                acc[6] += wA*vA2.z + wB*vB2.z; acc[7] += wA*vA2.w + wB*vB2.w;
                dn += wA + wB;
            } else {
                edge_accum(cA, lane, q, acc, dn);
            }
        }
    }

    float* op = g_attn + (size_t)row * Dd + lane * 8;
    const float* vs = g_vsum + lane * 8;
    float inv_d = 1.0f / ((float)Nn + dn);
    float4 o1, o2;
    o1.x = tf32_rna((vs[0] + acc[0]) * inv_d);
    o1.y = tf32_rna((vs[1] + acc[1]) * inv_d);
    o1.z = tf32_rna((vs[2] + acc[2]) * inv_d);
    o1.w = tf32_rna((vs[3] + acc[3]) * inv_d);
    o2.x = tf32_rna((vs[4] + acc[4]) * inv_d);
    o2.y = tf32_rna((vs[5] + acc[5]) * inv_d);
    o2.z = tf32_rna((vs[6] + acc[6]) * inv_d);
    o2.w = tf32_rna((vs[7] + acc[7]) * inv_d);
    *(float4*)op = o1;
    *(float4*)(op + 4) = o2;
}

// ---------------------------------------------------------------------------
extern "C" void kernel_launch(void* const* d_in, const int* in_sizes, int n_in,
                              void* d_out, int out_size) {
    const float* x  = (const float*)d_in[0];
    const int*   ei = (const int*)d_in[1];     // int32 (JAX x64 disabled)
    const float* Wq = (const float*)d_in[2];
    const float* Wk = (const float*)d_in[3];
    const float* Wv = (const float*)d_in[4];
    const float* Wo = (const float*)d_in[5];
    const float* bo = (const float*)d_in[6];
    float*       out = (float*)d_out;

    zero_small_kernel<<<17, 256>>>();
    bucket_kernel<<<Ee / 256, 256>>>(ei);
    round_kernel<<<512, 256>>>(x, Wq, Wk, Wv, Wo);
    gemm_qkv_kernel<<<dim3(Dd / 64, Nn / 64, 3), 128>>>();
    vsum_kernel<<<Nn / 16, 256>>>();
    row_kernel<<<Nn / 8, 256>>>();
    gemm_out_kernel<<<dim3(Dd / 64, Nn / 64, 1), 128>>>(bo, out);
}

// round 11
// speedup vs baseline: 1.0962x; 1.0962x over previous
#include <cuda_runtime.h>

// Problem constants
constexpr int Nn = 4096;   // nodes
constexpr int Dd = 256;    // model dim
constexpr int Ee = 65536;  // edges
constexpr int DCAP = 64;   // per-row bucket capacity (Poisson(16): P(deg>64) ~ 1e-19)

// QKV GEMM (BM128/BN128/BK16) — R6's measured-best config
constexpr int BK1   = 16;
constexpr int KP1   = 20;   // banks (20r+c)&31 all distinct for fragment loads
// Out GEMM (BM64/BN128/BK32) — R8's config (better grid for 1 GEMM: 128 CTAs)
constexpr int BK2   = 32;
constexpr int KP2   = 36;   // banks (36r+c)&31=(4r+c)&31 all distinct
constexpr int SMEM_A2 = 64 * KP2;
constexpr int SMEM_W2 = 128 * KP2;
constexpr int SMEM2_BYTES = 2 * (SMEM_A2 + SMEM_W2) * 4;  // 55296

// ---------------------------------------------------------------------------
// Scratch
// ---------------------------------------------------------------------------
__device__ float    g_Q[Nn * Dd];
__device__ float    g_K[Nn * Dd];
__device__ float    g_V[Nn * Dd];
__device__ float    g_attn[Nn * Dd];
__device__ float    g_vsum[Dd];
__device__ int      g_cnt[Nn];
__device__ int      g_adj[Nn * DCAP];
// tf32-rounded operands
__device__ float    g_xr[Nn * Dd];
__device__ float    g_Wqr[Dd * Dd];
__device__ float    g_Wkr[Dd * Dd];
__device__ float    g_Wvr[Dd * Dd];
__device__ float    g_Wor[Dd * Dd];

// ---------------------------------------------------------------------------
__device__ __forceinline__ float tf32_rna(float f) {
    unsigned u;
    asm("cvt.rna.tf32.f32 %0, %1;" : "=r"(u) : "f"(f));
    return __uint_as_float(u);
}

__global__ void zero_small_kernel() {
    int idx = blockIdx.x * blockDim.x + threadIdx.x;
    if (idx < Nn) g_cnt[idx] = 0;
    if (idx < Dd) g_vsum[idx] = 0.0f;
}

__global__ void bucket_kernel(const int* __restrict__ ei) {
    int e = blockIdx.x * blockDim.x + threadIdx.x;
    if (e >= Ee) return;
    int row = ei[e] & (Nn - 1);
    int col = ei[Ee + e] & (Nn - 1);
    int p = atomicAdd(&g_cnt[row], 1);
    if (p < DCAP) g_adj[row * DCAP + p] = col;
}

__global__ void round_kernel(const float* __restrict__ x,
                             const float* __restrict__ Wq,
                             const float* __restrict__ Wk,
                             const float* __restrict__ Wv,
                             const float* __restrict__ Wo) {
    int idx = blockIdx.x * blockDim.x + threadIdx.x;
    int stride = gridDim.x * blockDim.x;
    for (int i = idx; i < Nn * Dd; i += stride) g_xr[i] = tf32_rna(x[i]);
    for (int i = idx; i < Dd * Dd; i += stride) {
        g_Wqr[i] = tf32_rna(Wq[i]);
        g_Wkr[i] = tf32_rna(Wk[i]);
        g_Wvr[i] = tf32_rna(Wv[i]);
        g_Wor[i] = tf32_rna(Wo[i]);
    }
}

// ---------------------------------------------------------------------------
// Shared GEMM helpers
// ---------------------------------------------------------------------------
__device__ __forceinline__ unsigned smem_u32(const void* p) {
    return (unsigned)__cvta_generic_to_shared(p);
}
__device__ __forceinline__ void cp_async16(unsigned dst, const void* src) {
    asm volatile("cp.async.cg.shared.global [%0], [%1], 16;" :: "r"(dst), "l"(src));
}
__device__ __forceinline__ void cp_commit() {
    asm volatile("cp.async.commit_group;" ::: "memory");
}
template <int N> __device__ __forceinline__ void cp_wait() {
    asm volatile("cp.async.wait_group %0;" :: "n"(N) : "memory");
}
__device__ __forceinline__ void mma_tf32(float* d, float a0, float a1, float a2, float a3,
                                         float b0, float b1) {
    asm volatile(
        "mma.sync.aligned.m16n8k8.row.col.f32.tf32.tf32.f32 "
        "{%0,%1,%2,%3}, {%4,%5,%6,%7}, {%8,%9}, {%0,%1,%2,%3};\n"
        : "+f"(d[0]), "+f"(d[1]), "+f"(d[2]), "+f"(d[3])
        : "r"(__float_as_uint(a0)), "r"(__float_as_uint(a1)),
          "r"(__float_as_uint(a2)), "r"(__float_as_uint(a3)),
          "r"(__float_as_uint(b0)), "r"(__float_as_uint(b1)));
}

// ---------------------------------------------------------------------------
// GEMM body #1 (QKV): BM=128, BN=128, BK=16, 256 thr, 8 warps (2m x 4n),
// warp tile 64x32. Static 40KB smem. Measured 25.0us for the 3 QKV GEMMs.
// ---------------------------------------------------------------------------
__device__ __forceinline__ void gemm_body_128(const float* __restrict__ A,
                                              const float* __restrict__ W,
                                              float* __restrict__ C) {
    __shared__ __align__(16) float As[2][128 * KP1];
    __shared__ __align__(16) float Ws[2][128 * KP1];

    const int tid  = threadIdx.x;
    const int lane = tid & 31;
    const int wid  = tid >> 5;
    const int wm0  = (wid & 1) * 64;
    const int wn0  = (wid >> 1) * 32;
    const int m0   = blockIdx.y * 128;
    const int n0   = blockIdx.x * 128;

    const int r = lane >> 2;
    const int c = lane & 3;

    const int ldrow = tid >> 2;        // 0..63
    const int ldk   = (tid & 3) * 4;   // 0,4,8,12

    float d[4][4][4];
#pragma unroll
    for (int i = 0; i < 4; i++)
#pragma unroll
        for (int j = 0; j < 4; j++)
#pragma unroll
            for (int q = 0; q < 4; q++) d[i][j][q] = 0.0f;

    auto do_stage = [&](int s, int t) {
        unsigned a_dst = smem_u32(&As[s][ldrow * KP1 + ldk]);
        cp_async16(a_dst, &A[(size_t)(m0 + ldrow) * Dd + t * BK1 + ldk]);
        cp_async16(a_dst + 64 * KP1 * 4, &A[(size_t)(m0 + ldrow + 64) * Dd + t * BK1 + ldk]);
        unsigned w_dst = smem_u32(&Ws[s][ldrow * KP1 + ldk]);
        cp_async16(w_dst, &W[(size_t)(n0 + ldrow) * Dd + t * BK1 + ldk]);
        cp_async16(w_dst + 64 * KP1 * 4, &W[(size_t)(n0 + ldrow + 64) * Dd + t * BK1 + ldk]);
        cp_commit();
    };

    do_stage(0, 0);

    constexpr int NT = Dd / BK1;  // 16
    for (int t = 0; t < NT; t++) {
        if (t + 1 < NT) { do_stage((t + 1) & 1, t + 1); cp_wait<1>(); }
        else            { cp_wait<0>(); }
        __syncthreads();
        const int s = t & 1;

#pragma unroll
        for (int kk = 0; kk < BK1; kk += 8) {
            float a[4][4], b[4][2];
#pragma unroll
            for (int i = 0; i < 4; i++) {
                const float* p = &As[s][(wm0 + 16 * i + r) * KP1 + kk + c];
                a[i][0] = p[0];
                a[i][1] = p[8 * KP1];
                a[i][2] = p[4];
                a[i][3] = p[8 * KP1 + 4];
            }
#pragma unroll
            for (int j = 0; j < 4; j++) {
                const float* p = &Ws[s][(wn0 + 8 * j + r) * KP1 + kk + c];
                b[j][0] = p[0];
                b[j][1] = p[4];
            }
#pragma unroll
            for (int i = 0; i < 4; i++)
#pragma unroll
                for (int j = 0; j < 4; j++)
                    mma_tf32(d[i][j], a[i][0], a[i][1], a[i][2], a[i][3],
                             b[j][0], b[j][1]);
        }
        __syncthreads();
    }

#pragma unroll
    for (int i = 0; i < 4; i++) {
#pragma unroll
        for (int j = 0; j < 4; j++) {
            int m = m0 + wm0 + 16 * i + r;
            int n = n0 + wn0 + 8 * j + 2 * c;
            *(float2*)&C[(size_t)m * Dd + n] = make_float2(d[i][j][0], d[i][j][1]);
            *(float2*)&C[(size_t)(m + 8) * Dd + n] = make_float2(d[i][j][2], d[i][j][3]);
        }
    }
}

__global__ __launch_bounds__(256) void gemm_qkv_kernel() {
    const float* W = (blockIdx.z == 0) ? g_Wqr : (blockIdx.z == 1) ? g_Wkr : g_Wvr;
    float* C = (blockIdx.z == 0) ? g_Q : (blockIdx.z == 1) ? g_K : g_V;
    gemm_body_128(g_xr, W, C);
}

// ---------------------------------------------------------------------------
// GEMM body #2 (out-proj): BM=64, BN=128, BK=32, 256 thr, warp tile 32x32.
// Dynamic 55KB smem; grid = 128 CTAs for the single out GEMM.
// ---------------------------------------------------------------------------
__global__ __launch_bounds__(256, 3) void gemm_out_kernel(const float* __restrict__ bo,
                                                          float* __restrict__ out) {
    extern __shared__ __align__(16) float smem[];
    float* As0 = smem;
    float* Ws0 = smem + 2 * SMEM_A2;

    const float* A = g_attn;
    const float* W = g_Wor;

    const int tid  = threadIdx.x;
    const int lane = tid & 31;
    const int wid  = tid >> 5;
    const int wm0  = (wid & 1) * 32;
    const int wn0  = (wid >> 1) * 32;
    const int m0   = blockIdx.y * 64;
    const int n0   = blockIdx.x * 128;

    const int r = lane >> 2;
    const int c = lane & 3;

    const int rA = tid >> 2;          // 0..63
    const int kA = (tid & 3) * 8;     // 0,8,16,24
    const int rW = tid >> 1;          // 0..127
    const int kW = (tid & 1) * 16;    // 0,16

    float d[2][4][4];
#pragma unroll
    for (int i = 0; i < 2; i++)
#pragma unroll
        for (int j = 0; j < 4; j++)
#pragma unroll
            for (int q = 0; q < 4; q++) d[i][j][q] = 0.0f;

    auto do_stage = [&](int s, int t) {
        float* As = As0 + s * SMEM_A2;
        float* Ws = Ws0 + s * SMEM_W2;
        unsigned a_dst = smem_u32(&As[rA * KP2 + kA]);
        const float* a_src = &A[(size_t)(m0 + rA) * Dd + t * BK2 + kA];
        cp_async16(a_dst,      a_src);
        cp_async16(a_dst + 16, a_src + 4);
        unsigned w_dst = smem_u32(&Ws[rW * KP2 + kW]);
        const float* w_src = &W[(size_t)(n0 + rW) * Dd + t * BK2 + kW];
        cp_async16(w_dst,      w_src);
        cp_async16(w_dst + 16, w_src + 4);
        cp_async16(w_dst + 32, w_src + 8);
        cp_async16(w_dst + 48, w_src + 12);
        cp_commit();
    };

    do_stage(0, 0);

    constexpr int NT = Dd / BK2;  // 8
    for (int t = 0; t < NT; t++) {
        if (t + 1 < NT) { do_stage((t + 1) & 1, t + 1); cp_wait<1>(); }
        else            { cp_wait<0>(); }
        __syncthreads();
        const int s = t & 1;
        const float* As = As0 + s * SMEM_A2;
        const float* Ws = Ws0 + s * SMEM_W2;

#pragma unroll
        for (int kk = 0; kk < BK2; kk += 8) {
            float a[2][4], b[4][2];
#pragma unroll
            for (int i = 0; i < 2; i++) {
                const float* p = &As[(wm0 + 16 * i + r) * KP2 + kk + c];
                a[i][0] = p[0];
                a[i][1] = p[8 * KP2];
                a[i][2] = p[4];
                a[i][3] = p[8 * KP2 + 4];
            }
#pragma unroll
            for (int j = 0; j < 4; j++) {
                const float* p = &Ws[(wn0 + 8 * j + r) * KP2 + kk + c];
                b[j][0] = p[0];
                b[j][1] = p[4];
            }
#pragma unroll
            for (int i = 0; i < 2; i++)
#pragma unroll
                for (int j = 0; j < 4; j++)
                    mma_tf32(d[i][j], a[i][0], a[i][1], a[i][2], a[i][3],
                             b[j][0], b[j][1]);
        }
        __syncthreads();
    }

#pragma unroll
    for (int i = 0; i < 2; i++) {
#pragma unroll
        for (int j = 0; j < 4; j++) {
            int m = m0 + wm0 + 16 * i + r;
            int n = n0 + wn0 + 8 * j + 2 * c;
            float bx = bo[n], by = bo[n + 1];
            *(float2*)&out[(size_t)m * Dd + n] =
                make_float2(d[i][j][0] + bx, d[i][j][1] + by);
            *(float2*)&out[(size_t)(m + 8) * Dd + n] =
                make_float2(d[i][j][2] + bx, d[i][j][3] + by);
        }
    }
}

// ---------------------------------------------------------------------------
// Column sums of V
// ---------------------------------------------------------------------------
__global__ void vsum_kernel() {
    int c = threadIdx.x;
    int r0 = blockIdx.x * 16;
    float s = 0.0f;
#pragma unroll
    for (int r = 0; r < 16; r++) s += g_V[(size_t)(r0 + r) * Dd + c];
    atomicAdd(&g_vsum[c], s);
}

// ---------------------------------------------------------------------------
// Row kernel: one WARP per row (R6/R8 winner).
// ---------------------------------------------------------------------------
__device__ __forceinline__ void edge_accum(int col, int lane, const float* q,
                                           float* acc, float& dn) {
    const float* kp = g_K + (size_t)col * Dd + lane * 8;
    const float* vp = g_V + (size_t)col * Dd + lane * 8;
    float4 k1 = *(const float4*)kp;
    float4 k2 = *(const float4*)(kp + 4);
    float4 v1 = *(const float4*)vp;
    float4 v2 = *(const float4*)(vp + 4);
    float s = q[0] * k1.x + q[1] * k1.y + q[2] * k1.z + q[3] * k1.w
            + q[4] * k2.x + q[5] * k2.y + q[6] * k2.z + q[7] * k2.w;
    s += __shfl_xor_sync(0xffffffffu, s, 1);
    s += __shfl_xor_sync(0xffffffffu, s, 2);
    const float inv_scale = 0.17677669529663687f;
    float w = __expf(s * inv_scale) - 1.0f;
    acc[0] += w * v1.x; acc[1] += w * v1.y; acc[2] += w * v1.z; acc[3] += w * v1.w;
    acc[4] += w * v2.x; acc[5] += w * v2.y; acc[6] += w * v2.z; acc[7] += w * v2.w;
    dn += w;
}

__global__ __launch_bounds__(256) void row_kernel() {
    const int lane = threadIdx.x & 31;
    const int row  = blockIdx.x * 8 + (threadIdx.x >> 5);

    const int deg = min(g_cnt[row], DCAP);
    const int* adj = g_adj + row * DCAP;

    int col0 = (lane < deg)      ? adj[lane]      : (-1 - lane);
    int col1 = (32 + lane < deg) ? adj[32 + lane] : (-1 - lane);

    unsigned m0 = __match_any_sync(0xffffffffu, col0);
    bool keep0 = (lane < deg) && (lane == __ffs(m0) - 1);
    unsigned bm0 = __ballot_sync(0xffffffffu, keep0);

    unsigned bm1 = 0u;
    if (deg > 32) {
        unsigned m1 = __match_any_sync(0xffffffffu, col1);
        bool keep1 = (32 + lane < deg) && (lane == __ffs(m1) - 1);
        for (int j = 0; j < 32; j++) {
            int cj = __shfl_sync(0xffffffffu, col0, j);
            if (j < deg && cj == col1) keep1 = false;
        }
        bm1 = __ballot_sync(0xffffffffu, keep1);
    }

    float q[8];
    {
        const float* qp = g_Q + (size_t)row * Dd + lane * 8;
        float4 a = *(const float4*)qp;
        float4 b = *(const float4*)(qp + 4);
        q[0] = a.x; q[1] = a.y; q[2] = a.z; q[3] = a.w;
        q[4] = b.x; q[5] = b.y; q[6] = b.z; q[7] = b.w;
    }

    float acc[8] = {0, 0, 0, 0, 0, 0, 0, 0};
    float dn = 0.0f;

#pragma unroll 1
    for (int ch = 0; ch < 2; ch++) {
        unsigned bm = (ch == 0) ? bm0 : bm1;
        int cols = (ch == 0) ? col0 : col1;
        while (bm) {
            int b0 = __ffs(bm) - 1; bm &= bm - 1;
            int cA = __shfl_sync(0xffffffffu, cols, b0);
            if (bm) {
                int b1 = __ffs(bm) - 1; bm &= bm - 1;
                int cB = __shfl_sync(0xffffffffu, cols, b1);
                const float* kA = g_K + (size_t)cA * Dd + lane * 8;
                const float* vA = g_V + (size_t)cA * Dd + lane * 8;
                const float* kB = g_K + (size_t)cB * Dd + lane * 8;
                const float* vB = g_V + (size_t)cB * Dd + lane * 8;
                float4 kA1 = *(const float4*)kA, kA2 = *(const float4*)(kA + 4);
                float4 vA1 = *(const float4*)vA, vA2 = *(const float4*)(vA + 4);
                float4 kB1 = *(const float4*)kB, kB2 = *(const float4*)(kB + 4);
                float4 vB1 = *(const float4*)vB, vB2 = *(const float4*)(vB + 4);

                float sA = q[0]*kA1.x + q[1]*kA1.y + q[2]*kA1.z + q[3]*kA1.w
                         + q[4]*kA2.x + q[5]*kA2.y + q[6]*kA2.z + q[7]*kA2.w;
                float sB = q[0]*kB1.x + q[1]*kB1.y + q[2]*kB1.z + q[3]*kB1.w
                         + q[4]*kB2.x + q[5]*kB2.y + q[6]*kB2.z + q[7]*kB2.w;
                sA += __shfl_xor_sync(0xffffffffu, sA, 1);
                sB += __shfl_xor_sync(0xffffffffu, sB, 1);
                sA += __shfl_xor_sync(0xffffffffu, sA, 2);
                sB += __shfl_xor_sync(0xffffffffu, sB, 2);
                const float inv_scale = 0.17677669529663687f;
                float wA = __expf(sA * inv_scale) - 1.0f;
                float wB = __expf(sB * inv_scale) - 1.0f;
                acc[0] += wA*vA1.x + wB*vB1.x; acc[1] += wA*vA1.y + wB*vB1.y;
                acc[2] += wA*vA1.z + wB*vB1.z; acc[3] += wA*vA1.w + wB*vB1.w;
                acc[4] += wA*vA2.x + wB*vB2.x; acc[5] += wA*vA2.y + wB*vB2.y;
                acc[6] += wA*vA2.z + wB*vB2.z; acc[7] += wA*vA2.w + wB*vB2.w;
                dn += wA + wB;
            } else {
                edge_accum(cA, lane, q, acc, dn);
            }
        }
    }

    float* op = g_attn + (size_t)row * Dd + lane * 8;
    const float* vs = g_vsum + lane * 8;
    float inv_d = 1.0f / ((float)Nn + dn);
    float4 o1, o2;
    o1.x = tf32_rna((vs[0] + acc[0]) * inv_d);
    o1.y = tf32_rna((vs[1] + acc[1]) * inv_d);
    o1.z = tf32_rna((vs[2] + acc[2]) * inv_d);
    o1.w = tf32_rna((vs[3] + acc[3]) * inv_d);
    o2.x = tf32_rna((vs[4] + acc[4]) * inv_d);
    o2.y = tf32_rna((vs[5] + acc[5]) * inv_d);
    o2.z = tf32_rna((vs[6] + acc[6]) * inv_d);
    o2.w = tf32_rna((vs[7] + acc[7]) * inv_d);
    *(float4*)op = o1;
    *(float4*)(op + 4) = o2;
}

// ---------------------------------------------------------------------------
extern "C" void kernel_launch(void* const* d_in, const int* in_sizes, int n_in,
                              void* d_out, int out_size) {
    const float* x  = (const float*)d_in[0];
    const int*   ei = (const int*)d_in[1];     // int32 (JAX x64 disabled)
    const float* Wq = (const float*)d_in[2];
    const float* Wk = (const float*)d_in[3];
    const float* Wv = (const float*)d_in[4];
    const float* Wo = (const float*)d_in[5];
    const float* bo = (const float*)d_in[6];
    float*       out = (float*)d_out;

    cudaFuncSetAttribute(gemm_out_kernel,
                         cudaFuncAttributeMaxDynamicSharedMemorySize, SMEM2_BYTES);

    zero_small_kernel<<<17, 256>>>();
    bucket_kernel<<<Ee / 256, 256>>>(ei);
    round_kernel<<<512, 256>>>(x, Wq, Wk, Wv, Wo);
    gemm_qkv_kernel<<<dim3(Dd / 128, Nn / 128, 3), 256>>>();
    vsum_kernel<<<Nn / 16, 256>>>();
    row_kernel<<<Nn / 8, 256>>>();
    gemm_out_kernel<<<dim3(Dd / 128, Nn / 64, 1), 256, SMEM2_BYTES>>>(bo, out);
}

// round 12
// speedup vs baseline: 1.2089x; 1.1029x over previous
#include <cuda_runtime.h>

// Problem constants
constexpr int Nn = 4096;   // nodes
constexpr int Dd = 256;    // model dim
constexpr int Ee = 65536;  // edges
constexpr int DCAP = 64;   // per-row bucket capacity

// Out GEMM (R11 config, unchanged)
constexpr int BK2 = 32;
constexpr int KP2 = 36;
constexpr int SMEM_A2 = 64 * KP2;
constexpr int SMEM_W2 = 128 * KP2;
constexpr int SMEM2_BYTES = 2 * (SMEM_A2 + SMEM_W2) * 4;  // 55296

// QKV GEMM: fragment-linear permuted operands, 4-stage cp.async ring
constexpr int QKV_STAGES = 4;
constexpr int STAGE_FLOATS = 4096;   // 2048 A + 2048 W per k-tile of 16
constexpr int QKV_SMEM_BYTES = QKV_STAGES * STAGE_FLOATS * 4;  // 65536

// ---------------------------------------------------------------------------
// Scratch
// ---------------------------------------------------------------------------
__device__ float    g_Q[Nn * Dd];
__device__ float    g_K[Nn * Dd];
__device__ float    g_V[Nn * Dd];
__device__ float    g_attn[Nn * Dd];
__device__ float    g_vsum[Dd];
__device__ int      g_cnt[Nn];
__device__ int      g_adj[Nn * DCAP];
// permuted (fragment-linear) tf32-rounded operands for the QKV GEMM
__device__ float    g_xp[Nn * Dd];
__device__ float    g_Wqp[Dd * Dd];
__device__ float    g_Wkp[Dd * Dd];
__device__ float    g_Wvp[Dd * Dd];
// standard-layout rounded Wo for the out-GEMM
__device__ float    g_Wor[Dd * Dd];

// ---------------------------------------------------------------------------
__device__ __forceinline__ float tf32_rna(float f) {
    unsigned u;
    asm("cvt.rna.tf32.f32 %0, %1;" : "=r"(u) : "f"(f));
    return __uint_as_float(u);
}

__global__ void zero_small_kernel() {
    int idx = blockIdx.x * blockDim.x + threadIdx.x;
    if (idx < Nn) g_cnt[idx] = 0;
    if (idx < Dd) g_vsum[idx] = 0.0f;
}

__global__ void bucket_kernel(const int* __restrict__ ei) {
    int e = blockIdx.x * blockDim.x + threadIdx.x;
    if (e >= Ee) return;
    int row = ei[e] & (Nn - 1);
    int col = ei[Ee + e] & (Nn - 1);
    int p = atomicAdd(&g_cnt[row], 1);
    if (p < DCAP) g_adj[row * DCAP + p] = col;
}

// ---------------------------------------------------------------------------
// Permute + tf32-round pass.
// A layout (x): float4 chunk index = (((mpanel*16 + kblk)*8 + mblk)*2 + kk)*32 + lane
//   chunk = { A[m][k], A[m+8][k], A[m][k+4], A[m+8][k+4] },
//   m = mpanel*128 + mblk*16 + (lane>>2), k = kblk*16 + kk*8 + (lane&3).
// B layout (W): chunk index = ((npanel*16 + kblk)*16 + nblk)*32 + lane
//   chunk = { W[n][kb], W[n][kb+4], W[n][kb+8], W[n][kb+12] },
//   n = npanel*128 + nblk*8 + (lane>>2), kb = kblk*16 + (lane&3).
// ---------------------------------------------------------------------------
__global__ void permute_kernel(const float* __restrict__ x,
                               const float* __restrict__ Wq,
                               const float* __restrict__ Wk,
                               const float* __restrict__ Wv,
                               const float* __restrict__ Wo) {
    int idx = blockIdx.x * blockDim.x + threadIdx.x;
    int stride = gridDim.x * blockDim.x;

    for (int cidx = idx; cidx < Nn * Dd / 4; cidx += stride) {
        int lane   = cidx & 31;
        int kk     = (cidx >> 5) & 1;
        int mblk   = (cidx >> 6) & 7;
        int kblk   = (cidx >> 9) & 15;
        int mpanel = cidx >> 13;
        int m = mpanel * 128 + mblk * 16 + (lane >> 2);
        int k = kblk * 16 + kk * 8 + (lane & 3);
        float4 v;
        v.x = tf32_rna(x[(size_t)m * Dd + k]);
        v.y = tf32_rna(x[(size_t)(m + 8) * Dd + k]);
        v.z = tf32_rna(x[(size_t)m * Dd + k + 4]);
        v.w = tf32_rna(x[(size_t)(m + 8) * Dd + k + 4]);
        ((float4*)g_xp)[cidx] = v;
    }

    for (int cidx = idx; cidx < Dd * Dd / 4; cidx += stride) {
        int lane   = cidx & 31;
        int nblk   = (cidx >> 5) & 15;
        int kblk   = (cidx >> 9) & 15;
        int npanel = cidx >> 13;
        int n  = npanel * 128 + nblk * 8 + (lane >> 2);
        int kb = kblk * 16 + (lane & 3);
        size_t s = (size_t)n * Dd + kb;
        float4 vq, vk, vv;
        vq.x = tf32_rna(Wq[s]);      vq.y = tf32_rna(Wq[s + 4]);
        vq.z = tf32_rna(Wq[s + 8]);  vq.w = tf32_rna(Wq[s + 12]);
        vk.x = tf32_rna(Wk[s]);      vk.y = tf32_rna(Wk[s + 4]);
        vk.z = tf32_rna(Wk[s + 8]);  vk.w = tf32_rna(Wk[s + 12]);
        vv.x = tf32_rna(Wv[s]);      vv.y = tf32_rna(Wv[s + 4]);
        vv.z = tf32_rna(Wv[s + 8]);  vv.w = tf32_rna(Wv[s + 12]);
        ((float4*)g_Wqp)[cidx] = vq;
        ((float4*)g_Wkp)[cidx] = vk;
        ((float4*)g_Wvp)[cidx] = vv;
    }

    for (int i = idx; i < Dd * Dd; i += stride) g_Wor[i] = tf32_rna(Wo[i]);
}

// ---------------------------------------------------------------------------
// Shared GEMM helpers
// ---------------------------------------------------------------------------
__device__ __forceinline__ unsigned smem_u32(const void* p) {
    return (unsigned)__cvta_generic_to_shared(p);
}
__device__ __forceinline__ void cp_async16(unsigned dst, const void* src) {
    asm volatile("cp.async.cg.shared.global [%0], [%1], 16;" :: "r"(dst), "l"(src));
}
__device__ __forceinline__ void cp_commit() {
    asm volatile("cp.async.commit_group;" ::: "memory");
}
template <int N> __device__ __forceinline__ void cp_wait() {
    asm volatile("cp.async.wait_group %0;" :: "n"(N) : "memory");
}
__device__ __forceinline__ void mma_tf32(float* d, float a0, float a1, float a2, float a3,
                                         float b0, float b1) {
    asm volatile(
        "mma.sync.aligned.m16n8k8.row.col.f32.tf32.tf32.f32 "
        "{%0,%1,%2,%3}, {%4,%5,%6,%7}, {%8,%9}, {%0,%1,%2,%3};\n"
        : "+f"(d[0]), "+f"(d[1]), "+f"(d[2]), "+f"(d[3])
        : "r"(__float_as_uint(a0)), "r"(__float_as_uint(a1)),
          "r"(__float_as_uint(a2)), "r"(__float_as_uint(a3)),
          "r"(__float_as_uint(b0)), "r"(__float_as_uint(b1)));
}

// ---------------------------------------------------------------------------
// QKV GEMM, fragment-linear: BM=128, BN=128, 256 thr, warp tile 64x32.
// Mainloop per tile: 4 B LDS.128 + 8 A LDS.128 + 32 mma (was 48 LDS.32 + 32).
// Staging is a pure linear 16KB copy per tile (4 cp.async/thread).
// ---------------------------------------------------------------------------
__global__ __launch_bounds__(256, 2) void gemm_qkv_kernel() {
    extern __shared__ __align__(16) float smem[];
    const float* Wp = (blockIdx.z == 0) ? g_Wqp : (blockIdx.z == 1) ? g_Wkp : g_Wvp;
    float* C = (blockIdx.z == 0) ? g_Q : (blockIdx.z == 1) ? g_K : g_V;

    const int tid  = threadIdx.x;
    const int lane = tid & 31;
    const int wid  = tid >> 5;
    const unsigned sbase = smem_u32(smem);

    float d[4][4][4];
#pragma unroll
    for (int i = 0; i < 4; i++)
#pragma unroll
        for (int j = 0; j < 4; j++)
#pragma unroll
            for (int q = 0; q < 4; q++) d[i][j][q] = 0.0f;

    auto stage = [&](int s, int t) {
        unsigned dstA = sbase + (unsigned)(s * STAGE_FLOATS) * 4u;
        const float* srcA = g_xp + ((size_t)blockIdx.y * 16 + t) * 2048;
        cp_async16(dstA + tid * 16, srcA + tid * 4);
        cp_async16(dstA + (tid + 256) * 16, srcA + (size_t)(tid + 256) * 4);
        unsigned dstW = dstA + 2048 * 4;
        const float* srcW = Wp + ((size_t)blockIdx.x * 16 + t) * 2048;
        cp_async16(dstW + tid * 16, srcW + tid * 4);
        cp_async16(dstW + (tid + 256) * 16, srcW + (size_t)(tid + 256) * 4);
        cp_commit();
    };

    stage(0, 0); stage(1, 1); stage(2, 2);

    constexpr int NT = Dd / 16;  // 16 k-tiles
    for (int t = 0; t < NT; t++) {
        if (t + 3 < NT) { stage((t + 3) & 3, t + 3); cp_wait<3>(); }
        else            { cp_wait<0>(); }
        __syncthreads();

        const float4* As4 = (const float4*)(smem + (t & 3) * STAGE_FLOATS);
        const float4* Ws4 = (const float4*)(smem + (t & 3) * STAGE_FLOATS + 2048);

        float4 bv[4];
#pragma unroll
        for (int j = 0; j < 4; j++)
            bv[j] = Ws4[((wid >> 1) * 4 + j) * 32 + lane];

#pragma unroll
        for (int kk = 0; kk < 2; kk++) {
            float4 av[4];
#pragma unroll
            for (int i = 0; i < 4; i++)
                av[i] = As4[(((wid & 1) * 4 + i) * 2 + kk) * 32 + lane];
#pragma unroll
            for (int i = 0; i < 4; i++)
#pragma unroll
                for (int j = 0; j < 4; j++)
                    mma_tf32(d[i][j], av[i].x, av[i].y, av[i].z, av[i].w,
                             kk ? bv[j].z : bv[j].x, kk ? bv[j].w : bv[j].y);
        }
        __syncthreads();
    }

    // Epilogue (same mapping as before)
    const int r = lane >> 2, c = lane & 3;
    const int wm0 = (wid & 1) * 64, wn0 = (wid >> 1) * 32;
    const int m0 = blockIdx.y * 128, n0 = blockIdx.x * 128;
#pragma unroll
    for (int i = 0; i < 4; i++) {
#pragma unroll
        for (int j = 0; j < 4; j++) {
            int m = m0 + wm0 + 16 * i + r;
            int n = n0 + wn0 + 8 * j + 2 * c;
            *(float2*)&C[(size_t)m * Dd + n] = make_float2(d[i][j][0], d[i][j][1]);
            *(float2*)&C[(size_t)(m + 8) * Dd + n] = make_float2(d[i][j][2], d[i][j][3]);
        }
    }
}

// ---------------------------------------------------------------------------
// Out-proj GEMM (R11 body, unchanged): BM=64, BN=128, BK=32, 128 CTAs.
// ---------------------------------------------------------------------------
__global__ __launch_bounds__(256, 3) void gemm_out_kernel(const float* __restrict__ bo,
                                                          float* __restrict__ out) {
    extern __shared__ __align__(16) float smem[];
    float* As0 = smem;
    float* Ws0 = smem + 2 * SMEM_A2;

    const float* A = g_attn;
    const float* W = g_Wor;

    const int tid  = threadIdx.x;
    const int lane = tid & 31;
    const int wid  = tid >> 5;
    const int wm0  = (wid & 1) * 32;
    const int wn0  = (wid >> 1) * 32;
    const int m0   = blockIdx.y * 64;
    const int n0   = blockIdx.x * 128;

    const int r = lane >> 2;
    const int c = lane & 3;

    const int rA = tid >> 2;
    const int kA = (tid & 3) * 8;
    const int rW = tid >> 1;
    const int kW = (tid & 1) * 16;

    float d[2][4][4];
#pragma unroll
    for (int i = 0; i < 2; i++)
#pragma unroll
        for (int j = 0; j < 4; j++)
#pragma unroll
            for (int q = 0; q < 4; q++) d[i][j][q] = 0.0f;

    auto do_stage = [&](int s, int t) {
        float* As = As0 + s * SMEM_A2;
        float* Ws = Ws0 + s * SMEM_W2;
        unsigned a_dst = smem_u32(&As[rA * KP2 + kA]);
        const float* a_src = &A[(size_t)(m0 + rA) * Dd + t * BK2 + kA];
        cp_async16(a_dst,      a_src);
        cp_async16(a_dst + 16, a_src + 4);
        unsigned w_dst = smem_u32(&Ws[rW * KP2 + kW]);
        const float* w_src = &W[(size_t)(n0 + rW) * Dd + t * BK2 + kW];
        cp_async16(w_dst,      w_src);
        cp_async16(w_dst + 16, w_src + 4);
        cp_async16(w_dst + 32, w_src + 8);
        cp_async16(w_dst + 48, w_src + 12);
        cp_commit();
    };

    do_stage(0, 0);

    constexpr int NT = Dd / BK2;
    for (int t = 0; t < NT; t++) {
        if (t + 1 < NT) { do_stage((t + 1) & 1, t + 1); cp_wait<1>(); }
        else            { cp_wait<0>(); }
        __syncthreads();
        const int s = t & 1;
        const float* As = As0 + s * SMEM_A2;
        const float* Ws = Ws0 + s * SMEM_W2;

#pragma unroll
        for (int kk = 0; kk < BK2; kk += 8) {
            float a[2][4], b[4][2];
#pragma unroll
            for (int i = 0; i < 2; i++) {
                const float* p = &As[(wm0 + 16 * i + r) * KP2 + kk + c];
                a[i][0] = p[0];
                a[i][1] = p[8 * KP2];
                a[i][2] = p[4];
                a[i][3] = p[8 * KP2 + 4];
            }
#pragma unroll
            for (int j = 0; j < 4; j++) {
                const float* p = &Ws[(wn0 + 8 * j + r) * KP2 + kk + c];
                b[j][0] = p[0];
                b[j][1] = p[4];
            }
#pragma unroll
            for (int i = 0; i < 2; i++)
#pragma unroll
                for (int j = 0; j < 4; j++)
                    mma_tf32(d[i][j], a[i][0], a[i][1], a[i][2], a[i][3],
                             b[j][0], b[j][1]);
        }
        __syncthreads();
    }

#pragma unroll
    for (int i = 0; i < 2; i++) {
#pragma unroll
        for (int j = 0; j < 4; j++) {
            int m = m0 + wm0 + 16 * i + r;
            int n = n0 + wn0 + 8 * j + 2 * c;
            float bx = bo[n], by = bo[n + 1];
            *(float2*)&out[(size_t)m * Dd + n] =
                make_float2(d[i][j][0] + bx, d[i][j][1] + by);
            *(float2*)&out[(size_t)(m + 8) * Dd + n] =
                make_float2(d[i][j][2] + bx, d[i][j][3] + by);
        }
    }
}

// ---------------------------------------------------------------------------
// Column sums of V
// ---------------------------------------------------------------------------
__global__ void vsum_kernel() {
    int c = threadIdx.x;
    int r0 = blockIdx.x * 16;
    float s = 0.0f;
#pragma unroll
    for (int r = 0; r < 16; r++) s += g_V[(size_t)(r0 + r) * Dd + c];
    atomicAdd(&g_vsum[c], s);
}

// ---------------------------------------------------------------------------
// Row kernel: one WARP per row (unchanged winner).
// ---------------------------------------------------------------------------
__device__ __forceinline__ void edge_accum(int col, int lane, const float* q,
                                           float* acc, float& dn) {
    const float* kp = g_K + (size_t)col * Dd + lane * 8;
    const float* vp = g_V + (size_t)col * Dd + lane * 8;
    float4 k1 = *(const float4*)kp;
    float4 k2 = *(const float4*)(kp + 4);
    float4 v1 = *(const float4*)vp;
    float4 v2 = *(const float4*)(vp + 4);
    float s = q[0] * k1.x + q[1] * k1.y + q[2] * k1.z + q[3] * k1.w
            + q[4] * k2.x + q[5] * k2.y + q[6] * k2.z + q[7] * k2.w;
    s += __shfl_xor_sync(0xffffffffu, s, 1);
    s += __shfl_xor_sync(0xffffffffu, s, 2);
    const float inv_scale = 0.17677669529663687f;
    float w = __expf(s * inv_scale) - 1.0f;
    acc[0] += w * v1.x; acc[1] += w * v1.y; acc[2] += w * v1.z; acc[3] += w * v1.w;
    acc[4] += w * v2.x; acc[5] += w * v2.y; acc[6] += w * v2.z; acc[7] += w * v2.w;
    dn += w;
}

__global__ __launch_bounds__(256) void row_kernel() {
    const int lane = threadIdx.x & 31;
    const int row  = blockIdx.x * 8 + (threadIdx.x >> 5);

    const int deg = min(g_cnt[row], DCAP);
    const int* adj = g_adj + row * DCAP;

    int col0 = (lane < deg)      ? adj[lane]      : (-1 - lane);
    int col1 = (32 + lane < deg) ? adj[32 + lane] : (-1 - lane);

    unsigned m0 = __match_any_sync(0xffffffffu, col0);
    bool keep0 = (lane < deg) && (lane == __ffs(m0) - 1);
    unsigned bm0 = __ballot_sync(0xffffffffu, keep0);

    unsigned bm1 = 0u;
    if (deg > 32) {
        unsigned m1 = __match_any_sync(0xffffffffu, col1);
        bool keep1 = (32 + lane < deg) && (lane == __ffs(m1) - 1);
        for (int j = 0; j < 32; j++) {
            int cj = __shfl_sync(0xffffffffu, col0, j);
            if (j < deg && cj == col1) keep1 = false;
        }
        bm1 = __ballot_sync(0xffffffffu, keep1);
    }

    float q[8];
    {
        const float* qp = g_Q + (size_t)row * Dd + lane * 8;
        float4 a = *(const float4*)qp;
        float4 b = *(const float4*)(qp + 4);
        q[0] = a.x; q[1] = a.y; q[2] = a.z; q[3] = a.w;
        q[4] = b.x; q[5] = b.y; q[6] = b.z; q[7] = b.w;
    }

    float acc[8] = {0, 0, 0, 0, 0, 0, 0, 0};
    float dn = 0.0f;

#pragma unroll 1
    for (int ch = 0; ch < 2; ch++) {
        unsigned bm = (ch == 0) ? bm0 : bm1;
        int cols = (ch == 0) ? col0 : col1;
        while (bm) {
            int b0 = __ffs(bm) - 1; bm &= bm - 1;
            int cA = __shfl_sync(0xffffffffu, cols, b0);
            if (bm) {
                int b1 = __ffs(bm) - 1; bm &= bm - 1;
                int cB = __shfl_sync(0xffffffffu, cols, b1);
                const float* kA = g_K + (size_t)cA * Dd + lane * 8;
                const float* vA = g_V + (size_t)cA * Dd + lane * 8;
                const float* kB = g_K + (size_t)cB * Dd + lane * 8;
                const float* vB = g_V + (size_t)cB * Dd + lane * 8;
                float4 kA1 = *(const float4*)kA, kA2 = *(const float4*)(kA + 4);
                float4 vA1 = *(const float4*)vA, vA2 = *(const float4*)(vA + 4);
                float4 kB1 = *(const float4*)kB, kB2 = *(const float4*)(kB + 4);
                float4 vB1 = *(const float4*)vB, vB2 = *(const float4*)(vB + 4);

                float sA = q[0]*kA1.x + q[1]*kA1.y + q[2]*kA1.z + q[3]*kA1.w
                         + q[4]*kA2.x + q[5]*kA2.y + q[6]*kA2.z + q[7]*kA2.w;
                float sB = q[0]*kB1.x + q[1]*kB1.y + q[2]*kB1.z + q[3]*kB1.w
                         + q[4]*kB2.x + q[5]*kB2.y + q[6]*kB2.z + q[7]*kB2.w;
                sA += __shfl_xor_sync(0xffffffffu, sA, 1);
                sB += __shfl_xor_sync(0xffffffffu, sB, 1);
                sA += __shfl_xor_sync(0xffffffffu, sA, 2);
                sB += __shfl_xor_sync(0xffffffffu, sB, 2);
                const float inv_scale = 0.17677669529663687f;
                float wA = __expf(sA * inv_scale) - 1.0f;
                float wB = __expf(sB * inv_scale) - 1.0f;
                acc[0] += wA*vA1.x + wB*vB1.x; acc[1] += wA*vA1.y + wB*vB1.y;
                acc[2] += wA*vA1.z + wB*vB1.z; acc[3] += wA*vA1.w + wB*vB1.w;
                acc[4] += wA*vA2.x + wB*vB2.x; acc[5] += wA*vA2.y + wB*vB2.y;
                acc[6] += wA*vA2.z + wB*vB2.z; acc[7] += wA*vA2.w + wB*vB2.w;
                dn += wA + wB;
            } else {
                edge_accum(cA, lane, q, acc, dn);
            }
        }
    }

    float* op = g_attn + (size_t)row * Dd + lane * 8;
    const float* vs = g_vsum + lane * 8;
    float inv_d = 1.0f / ((float)Nn + dn);
    float4 o1, o2;
    o1.x = tf32_rna((vs[0] + acc[0]) * inv_d);
    o1.y = tf32_rna((vs[1] + acc[1]) * inv_d);
    o1.z = tf32_rna((vs[2] + acc[2]) * inv_d);
    o1.w = tf32_rna((vs[3] + acc[3]) * inv_d);
    o2.x = tf32_rna((vs[4] + acc[4]) * inv_d);
    o2.y = tf32_rna((vs[5] + acc[5]) * inv_d);
    o2.z = tf32_rna((vs[6] + acc[6]) * inv_d);
    o2.w = tf32_rna((vs[7] + acc[7]) * inv_d);
    *(float4*)op = o1;
    *(float4*)(op + 4) = o2;
}

// ---------------------------------------------------------------------------
extern "C" void kernel_launch(void* const* d_in, const int* in_sizes, int n_in,
                              void* d_out, int out_size) {
    const float* x  = (const float*)d_in[0];
    const int*   ei = (const int*)d_in[1];     // int32 (JAX x64 disabled)
    const float* Wq = (const float*)d_in[2];
    const float* Wk = (const float*)d_in[3];
    const float* Wv = (const float*)d_in[4];
    const float* Wo = (const float*)d_in[5];
    const float* bo = (const float*)d_in[6];
    float*       out = (float*)d_out;

    cudaFuncSetAttribute(gemm_qkv_kernel,
                         cudaFuncAttributeMaxDynamicSharedMemorySize, QKV_SMEM_BYTES);
    cudaFuncSetAttribute(gemm_out_kernel,
                         cudaFuncAttributeMaxDynamicSharedMemorySize, SMEM2_BYTES);

    zero_small_kernel<<<17, 256>>>();
    bucket_kernel<<<Ee / 256, 256>>>(ei);
    permute_kernel<<<512, 256>>>(x, Wq, Wk, Wv, Wo);
    gemm_qkv_kernel<<<dim3(2, 32, 3), 256, QKV_SMEM_BYTES>>>();
    vsum_kernel<<<Nn / 16, 256>>>();
    row_kernel<<<Nn / 8, 256>>>();
    gemm_out_kernel<<<dim3(Dd / 128, Nn / 64, 1), 256, SMEM2_BYTES>>>(bo, out);
}

// round 13
// speedup vs baseline: 1.2992x; 1.0747x over previous
#include <cuda_runtime.h>

// Problem constants
constexpr int Nn = 4096;   // nodes
constexpr int Dd = 256;    // model dim
constexpr int Ee = 65536;  // edges
constexpr int DCAP = 64;   // per-row bucket capacity

// Out GEMM (R11/R12 config, unchanged)
constexpr int BK2 = 32;
constexpr int KP2 = 36;
constexpr int SMEM_A2 = 64 * KP2;
constexpr int SMEM_W2 = 128 * KP2;
constexpr int SMEM2_BYTES = 2 * (SMEM_A2 + SMEM_W2) * 4;  // 55296

// QKV GEMM: fragment-linear operands, BM=64/BN=128, 4-stage cp.async ring
constexpr int QKV_STAGES = 4;
constexpr int STAGE_FLOATS = 3072;   // 1024 A (64x16) + 2048 W (128x16)
constexpr int QKV_SMEM_BYTES = QKV_STAGES * STAGE_FLOATS * 4;  // 49152

// ---------------------------------------------------------------------------
// Scratch
// ---------------------------------------------------------------------------
__device__ float    g_Q[Nn * Dd];
__device__ float    g_K[Nn * Dd];
__device__ float    g_V[Nn * Dd];
__device__ float    g_attn[Nn * Dd];
__device__ float    g_vsum[Dd];
__device__ int      g_cnt[Nn];
__device__ int      g_adj[Nn * DCAP];
// permuted (fragment-linear) tf32-rounded operands for the QKV GEMM
__device__ float    g_xp[Nn * Dd];
__device__ float    g_Wqp[Dd * Dd];
__device__ float    g_Wkp[Dd * Dd];
__device__ float    g_Wvp[Dd * Dd];
// standard-layout rounded Wo for the out-GEMM
__device__ float    g_Wor[Dd * Dd];

// ---------------------------------------------------------------------------
__device__ __forceinline__ float tf32_rna(float f) {
    unsigned u;
    asm("cvt.rna.tf32.f32 %0, %1;" : "=r"(u) : "f"(f));
    return __uint_as_float(u);
}

__global__ void zero_small_kernel() {
    int idx = blockIdx.x * blockDim.x + threadIdx.x;
    if (idx < Nn) g_cnt[idx] = 0;
    if (idx < Dd) g_vsum[idx] = 0.0f;
}

__global__ void bucket_kernel(const int* __restrict__ ei) {
    int e = blockIdx.x * blockDim.x + threadIdx.x;
    if (e >= Ee) return;
    int row = ei[e] & (Nn - 1);
    int col = ei[Ee + e] & (Nn - 1);
    int p = atomicAdd(&g_cnt[row], 1);
    if (p < DCAP) g_adj[row * DCAP + p] = col;
}

// ---------------------------------------------------------------------------
// Permute + tf32-round pass (fragment-linear layouts; unchanged from R12).
// ---------------------------------------------------------------------------
__global__ void permute_kernel(const float* __restrict__ x,
                               const float* __restrict__ Wq,
                               const float* __restrict__ Wk,
                               const float* __restrict__ Wv,
                               const float* __restrict__ Wo) {
    int idx = blockIdx.x * blockDim.x + threadIdx.x;
    int stride = gridDim.x * blockDim.x;

    for (int cidx = idx; cidx < Nn * Dd / 4; cidx += stride) {
        int lane   = cidx & 31;
        int kk     = (cidx >> 5) & 1;
        int mblk   = (cidx >> 6) & 7;
        int kblk   = (cidx >> 9) & 15;
        int mpanel = cidx >> 13;
        int m = mpanel * 128 + mblk * 16 + (lane >> 2);
        int k = kblk * 16 + kk * 8 + (lane & 3);
        float4 v;
        v.x = tf32_rna(x[(size_t)m * Dd + k]);
        v.y = tf32_rna(x[(size_t)(m + 8) * Dd + k]);
        v.z = tf32_rna(x[(size_t)m * Dd + k + 4]);
        v.w = tf32_rna(x[(size_t)(m + 8) * Dd + k + 4]);
        ((float4*)g_xp)[cidx] = v;
    }

    for (int cidx = idx; cidx < Dd * Dd / 4; cidx += stride) {
        int lane   = cidx & 31;
        int nblk   = (cidx >> 5) & 15;
        int kblk   = (cidx >> 9) & 15;
        int npanel = cidx >> 13;
        int n  = npanel * 128 + nblk * 8 + (lane >> 2);
        int kb = kblk * 16 + (lane & 3);
        size_t s = (size_t)n * Dd + kb;
        float4 vq, vk, vv;
        vq.x = tf32_rna(Wq[s]);      vq.y = tf32_rna(Wq[s + 4]);
        vq.z = tf32_rna(Wq[s + 8]);  vq.w = tf32_rna(Wq[s + 12]);
        vk.x = tf32_rna(Wk[s]);      vk.y = tf32_rna(Wk[s + 4]);
        vk.z = tf32_rna(Wk[s + 8]);  vk.w = tf32_rna(Wk[s + 12]);
        vv.x = tf32_rna(Wv[s]);      vv.y = tf32_rna(Wv[s + 4]);
        vv.z = tf32_rna(Wv[s + 8]);  vv.w = tf32_rna(Wv[s + 12]);
        ((float4*)g_Wqp)[cidx] = vq;
        ((float4*)g_Wkp)[cidx] = vk;
        ((float4*)g_Wvp)[cidx] = vv;
    }

    for (int i = idx; i < Dd * Dd; i += stride) g_Wor[i] = tf32_rna(Wo[i]);
}

// ---------------------------------------------------------------------------
// Shared GEMM helpers
// ---------------------------------------------------------------------------
__device__ __forceinline__ unsigned smem_u32(const void* p) {
    return (unsigned)__cvta_generic_to_shared(p);
}
__device__ __forceinline__ void cp_async16(unsigned dst, const void* src) {
    asm volatile("cp.async.cg.shared.global [%0], [%1], 16;" :: "r"(dst), "l"(src));
}
__device__ __forceinline__ void cp_commit() {
    asm volatile("cp.async.commit_group;" ::: "memory");
}
template <int N> __device__ __forceinline__ void cp_wait() {
    asm volatile("cp.async.wait_group %0;" :: "n"(N) : "memory");
}
__device__ __forceinline__ void mma_tf32(float* d, float a0, float a1, float a2, float a3,
                                         float b0, float b1) {
    asm volatile(
        "mma.sync.aligned.m16n8k8.row.col.f32.tf32.tf32.f32 "
        "{%0,%1,%2,%3}, {%4,%5,%6,%7}, {%8,%9}, {%0,%1,%2,%3};\n"
        : "+f"(d[0]), "+f"(d[1]), "+f"(d[2]), "+f"(d[3])
        : "r"(__float_as_uint(a0)), "r"(__float_as_uint(a1)),
          "r"(__float_as_uint(a2)), "r"(__float_as_uint(a3)),
          "r"(__float_as_uint(b0)), "r"(__float_as_uint(b1)));
}

// ---------------------------------------------------------------------------
// QKV GEMM, fragment-linear, BM=64 / BN=128, 128 threads = 4 warps, each
// warp-tile 64x32 (A fragments broadcast across warps). 384 CTAs, 48KB smem,
// <=124 regs -> 4 CTAs/SM capacity: whole grid resident in ONE wave.
// ---------------------------------------------------------------------------
__global__ __launch_bounds__(128, 4) void gemm_qkv_kernel() {
    extern __shared__ __align__(16) float smem[];
    const float* Wp = (blockIdx.z == 0) ? g_Wqp : (blockIdx.z == 1) ? g_Wkp : g_Wvp;
    float* C = (blockIdx.z == 0) ? g_Q : (blockIdx.z == 1) ? g_K : g_V;

    const int tid  = threadIdx.x;
    const int lane = tid & 31;
    const int wid  = tid >> 5;          // 0..3 -> n-block group
    const unsigned sbase = smem_u32(smem);

    const int mp128 = blockIdx.y >> 1;  // 128-row panel in g_xp
    const int half  = blockIdx.y & 1;   // which 64-row half

    float d[4][4][4];
#pragma unroll
    for (int i = 0; i < 4; i++)
#pragma unroll
        for (int j = 0; j < 4; j++)
#pragma unroll
            for (int q = 0; q < 4; q++) d[i][j][q] = 0.0f;

    auto stage = [&](int s, int t) {
        unsigned dstA = sbase + (unsigned)(s * STAGE_FLOATS) * 4u;
        const float* srcA = g_xp + ((size_t)mp128 * 16 + t) * 2048 + half * 1024;
        cp_async16(dstA + tid * 16, srcA + (size_t)tid * 4);
        cp_async16(dstA + (tid + 128) * 16, srcA + (size_t)(tid + 128) * 4);
        unsigned dstW = dstA + 1024 * 4;
        const float* srcW = Wp + ((size_t)blockIdx.x * 16 + t) * 2048;
        cp_async16(dstW + tid * 16, srcW + (size_t)tid * 4);
        cp_async16(dstW + (tid + 128) * 16, srcW + (size_t)(tid + 128) * 4);
        cp_async16(dstW + (tid + 256) * 16, srcW + (size_t)(tid + 256) * 4);
        cp_async16(dstW + (tid + 384) * 16, srcW + (size_t)(tid + 384) * 4);
        cp_commit();
    };

    stage(0, 0); stage(1, 1); stage(2, 2);

    constexpr int NT = Dd / 16;  // 16 k-tiles
    for (int t = 0; t < NT; t++) {
        if (t + 3 < NT) { stage((t + 3) & 3, t + 3); cp_wait<3>(); }
        else            { cp_wait<0>(); }
        __syncthreads();

        const float4* As4 = (const float4*)(smem + (t & 3) * STAGE_FLOATS);
        const float4* Ws4 = (const float4*)(smem + (t & 3) * STAGE_FLOATS + 1024);

        float4 bv[4];
#pragma unroll
        for (int j = 0; j < 4; j++)
            bv[j] = Ws4[(wid * 4 + j) * 32 + lane];

#pragma unroll
        for (int kk = 0; kk < 2; kk++) {
            float4 av[4];
#pragma unroll
            for (int i = 0; i < 4; i++)
                av[i] = As4[(i * 2 + kk) * 32 + lane];
#pragma unroll
            for (int i = 0; i < 4; i++)
#pragma unroll
                for (int j = 0; j < 4; j++)
                    mma_tf32(d[i][j], av[i].x, av[i].y, av[i].z, av[i].w,
                             kk ? bv[j].z : bv[j].x, kk ? bv[j].w : bv[j].y);
        }
        __syncthreads();
    }

    // Epilogue
    const int r = lane >> 2, c = lane & 3;
    const int m0 = blockIdx.y * 64;
    const int n0 = blockIdx.x * 128 + wid * 32;
#pragma unroll
    for (int i = 0; i < 4; i++) {
#pragma unroll
        for (int j = 0; j < 4; j++) {
            int m = m0 + 16 * i + r;
            int n = n0 + 8 * j + 2 * c;
            *(float2*)&C[(size_t)m * Dd + n] = make_float2(d[i][j][0], d[i][j][1]);
            *(float2*)&C[(size_t)(m + 8) * Dd + n] = make_float2(d[i][j][2], d[i][j][3]);
        }
    }
}

// ---------------------------------------------------------------------------
// Out-proj GEMM (R11/R12 body, unchanged): BM=64, BN=128, BK=32, 128 CTAs.
// ---------------------------------------------------------------------------
__global__ __launch_bounds__(256, 3) void gemm_out_kernel(const float* __restrict__ bo,
                                                          float* __restrict__ out) {
    extern __shared__ __align__(16) float smem[];
    float* As0 = smem;
    float* Ws0 = smem + 2 * SMEM_A2;

    const float* A = g_attn;
    const float* W = g_Wor;

    const int tid  = threadIdx.x;
    const int lane = tid & 31;
    const int wid  = tid >> 5;
    const int wm0  = (wid & 1) * 32;
    const int wn0  = (wid >> 1) * 32;
    const int m0   = blockIdx.y * 64;
    const int n0   = blockIdx.x * 128;

    const int r = lane >> 2;
    const int c = lane & 3;

    const int rA = tid >> 2;
    const int kA = (tid & 3) * 8;
    const int rW = tid >> 1;
    const int kW = (tid & 1) * 16;

    float d[2][4][4];
#pragma unroll
    for (int i = 0; i < 2; i++)
#pragma unroll
        for (int j = 0; j < 4; j++)
#pragma unroll
            for (int q = 0; q < 4; q++) d[i][j][q] = 0.0f;

    auto do_stage = [&](int s, int t) {
        float* As = As0 + s * SMEM_A2;
        float* Ws = Ws0 + s * SMEM_W2;
        unsigned a_dst = smem_u32(&As[rA * KP2 + kA]);
        const float* a_src = &A[(size_t)(m0 + rA) * Dd + t * BK2 + kA];
        cp_async16(a_dst,      a_src);
        cp_async16(a_dst + 16, a_src + 4);
        unsigned w_dst = smem_u32(&Ws[rW * KP2 + kW]);
        const float* w_src = &W[(size_t)(n0 + rW) * Dd + t * BK2 + kW];
        cp_async16(w_dst,      w_src);
        cp_async16(w_dst + 16, w_src + 4);
        cp_async16(w_dst + 32, w_src + 8);
        cp_async16(w_dst + 48, w_src + 12);
        cp_commit();
    };

    do_stage(0, 0);

    constexpr int NT = Dd / BK2;
    for (int t = 0; t < NT; t++) {
        if (t + 1 < NT) { do_stage((t + 1) & 1, t + 1); cp_wait<1>(); }
        else            { cp_wait<0>(); }
        __syncthreads();
        const int s = t & 1;
        const float* As = As0 + s * SMEM_A2;
        const float* Ws = Ws0 + s * SMEM_W2;

#pragma unroll
        for (int kk = 0; kk < BK2; kk += 8) {
            float a[2][4], b[4][2];
#pragma unroll
            for (int i = 0; i < 2; i++) {
                const float* p = &As[(wm0 + 16 * i + r) * KP2 + kk + c];
                a[i][0] = p[0];
                a[i][1] = p[8 * KP2];
                a[i][2] = p[4];
                a[i][3] = p[8 * KP2 + 4];
            }
#pragma unroll
            for (int j = 0; j < 4; j++) {
                const float* p = &Ws[(wn0 + 8 * j + r) * KP2 + kk + c];
                b[j][0] = p[0];
                b[j][1] = p[4];
            }
#pragma unroll
            for (int i = 0; i < 2; i++)
#pragma unroll
                for (int j = 0; j < 4; j++)
                    mma_tf32(d[i][j], a[i][0], a[i][1], a[i][2], a[i][3],
                             b[j][0], b[j][1]);
        }
        __syncthreads();
    }

#pragma unroll
    for (int i = 0; i < 2; i++) {
#pragma unroll
        for (int j = 0; j < 4; j++) {
            int m = m0 + wm0 + 16 * i + r;
            int n = n0 + wn0 + 8 * j + 2 * c;
            float bx = bo[n], by = bo[n + 1];
            *(float2*)&out[(size_t)m * Dd + n] =
                make_float2(d[i][j][0] + bx, d[i][j][1] + by);
            *(float2*)&out[(size_t)(m + 8) * Dd + n] =
                make_float2(d[i][j][2] + bx, d[i][j][3] + by);
        }
    }
}

// ---------------------------------------------------------------------------
// Column sums of V
// ---------------------------------------------------------------------------
__global__ void vsum_kernel() {
    int c = threadIdx.x;
    int r0 = blockIdx.x * 16;
    float s = 0.0f;
#pragma unroll
    for (int r = 0; r < 16; r++) s += g_V[(size_t)(r0 + r) * Dd + c];
    atomicAdd(&g_vsum[c], s);
}

// ---------------------------------------------------------------------------
// Row kernel: one WARP per row (unchanged winner).
// ---------------------------------------------------------------------------
__device__ __forceinline__ void edge_accum(int col, int lane, const float* q,
                                           float* acc, float& dn) {
    const float* kp = g_K + (size_t)col * Dd + lane * 8;
    const float* vp = g_V + (size_t)col * Dd + lane * 8;
    float4 k1 = *(const float4*)kp;
    float4 k2 = *(const float4*)(kp + 4);
    float4 v1 = *(const float4*)vp;
    float4 v2 = *(const float4*)(vp + 4);
    float s = q[0] * k1.x + q[1] * k1.y + q[2] * k1.z + q[3] * k1.w
            + q[4] * k2.x + q[5] * k2.y + q[6] * k2.z + q[7] * k2.w;
    s += __shfl_xor_sync(0xffffffffu, s, 1);
    s += __shfl_xor_sync(0xffffffffu, s, 2);
    const float inv_scale = 0.17677669529663687f;
    float w = __expf(s * inv_scale) - 1.0f;
    acc[0] += w * v1.x; acc[1] += w * v1.y; acc[2] += w * v1.z; acc[3] += w * v1.w;
    acc[4] += w * v2.x; acc[5] += w * v2.y; acc[6] += w * v2.z; acc[7] += w * v2.w;
    dn += w;
}

__global__ __launch_bounds__(256) void row_kernel() {
    const int lane = threadIdx.x & 31;
    const int row  = blockIdx.x * 8 + (threadIdx.x >> 5);

    const int deg = min(g_cnt[row], DCAP);
    const int* adj = g_adj + row * DCAP;

    int col0 = (lane < deg)      ? adj[lane]      : (-1 - lane);
    int col1 = (32 + lane < deg) ? adj[32 + lane] : (-1 - lane);

    unsigned m0 = __match_any_sync(0xffffffffu, col0);
    bool keep0 = (lane < deg) && (lane == __ffs(m0) - 1);
    unsigned bm0 = __ballot_sync(0xffffffffu, keep0);

    unsigned bm1 = 0u;
    if (deg > 32) {
        unsigned m1 = __match_any_sync(0xffffffffu, col1);
        bool keep1 = (32 + lane < deg) && (lane == __ffs(m1) - 1);
        for (int j = 0; j < 32; j++) {
            int cj = __shfl_sync(0xffffffffu, col0, j);
            if (j < deg && cj == col1) keep1 = false;
        }
        bm1 = __ballot_sync(0xffffffffu, keep1);
    }

    float q[8];
    {
        const float* qp = g_Q + (size_t)row * Dd + lane * 8;
        float4 a = *(const float4*)qp;
        float4 b = *(const float4*)(qp + 4);
        q[0] = a.x; q[1] = a.y; q[2] = a.z; q[3] = a.w;
        q[4] = b.x; q[5] = b.y; q[6] = b.z; q[7] = b.w;
    }

    float acc[8] = {0, 0, 0, 0, 0, 0, 0, 0};
    float dn = 0.0f;

#pragma unroll 1
    for (int ch = 0; ch < 2; ch++) {
        unsigned bm = (ch == 0) ? bm0 : bm1;
        int cols = (ch == 0) ? col0 : col1;
        while (bm) {
            int b0 = __ffs(bm) - 1; bm &= bm - 1;
            int cA = __shfl_sync(0xffffffffu, cols, b0);
            if (bm) {
                int b1 = __ffs(bm) - 1; bm &= bm - 1;
                int cB = __shfl_sync(0xffffffffu, cols, b1);
                const float* kA = g_K + (size_t)cA * Dd + lane * 8;
                const float* vA = g_V + (size_t)cA * Dd + lane * 8;
                const float* kB = g_K + (size_t)cB * Dd + lane * 8;
                const float* vB = g_V + (size_t)cB * Dd + lane * 8;
                float4 kA1 = *(const float4*)kA, kA2 = *(const float4*)(kA + 4);
                float4 vA1 = *(const float4*)vA, vA2 = *(const float4*)(vA + 4);
                float4 kB1 = *(const float4*)kB, kB2 = *(const float4*)(kB + 4);
                float4 vB1 = *(const float4*)vB, vB2 = *(const float4*)(vB + 4);

                float sA = q[0]*kA1.x + q[1]*kA1.y + q[2]*kA1.z + q[3]*kA1.w
                         + q[4]*kA2.x + q[5]*kA2.y + q[6]*kA2.z + q[7]*kA2.w;
                float sB = q[0]*kB1.x + q[1]*kB1.y + q[2]*kB1.z + q[3]*kB1.w
                         + q[4]*kB2.x + q[5]*kB2.y + q[6]*kB2.z + q[7]*kB2.w;
                sA += __shfl_xor_sync(0xffffffffu, sA, 1);
                sB += __shfl_xor_sync(0xffffffffu, sB, 1);
                sA += __shfl_xor_sync(0xffffffffu, sA, 2);
                sB += __shfl_xor_sync(0xffffffffu, sB, 2);
                const float inv_scale = 0.17677669529663687f;
                float wA = __expf(sA * inv_scale) - 1.0f;
                float wB = __expf(sB * inv_scale) - 1.0f;
                acc[0] += wA*vA1.x + wB*vB1.x; acc[1] += wA*vA1.y + wB*vB1.y;
                acc[2] += wA*vA1.z + wB*vB1.z; acc[3] += wA*vA1.w + wB*vB1.w;
                acc[4] += wA*vA2.x + wB*vB2.x; acc[5] += wA*vA2.y + wB*vB2.y;
                acc[6] += wA*vA2.z + wB*vB2.z; acc[7] += wA*vA2.w + wB*vB2.w;
                dn += wA + wB;
            } else {
                edge_accum(cA, lane, q, acc, dn);
            }
        }
    }

    float* op = g_attn + (size_t)row * Dd + lane * 8;
    const float* vs = g_vsum + lane * 8;
    float inv_d = 1.0f / ((float)Nn + dn);
    float4 o1, o2;
    o1.x = tf32_rna((vs[0] + acc[0]) * inv_d);
    o1.y = tf32_rna((vs[1] + acc[1]) * inv_d);
    o1.z = tf32_rna((vs[2] + acc[2]) * inv_d);
    o1.w = tf32_rna((vs[3] + acc[3]) * inv_d);
    o2.x = tf32_rna((vs[4] + acc[4]) * inv_d);
    o2.y = tf32_rna((vs[5] + acc[5]) * inv_d);
    o2.z = tf32_rna((vs[6] + acc[6]) * inv_d);
    o2.w = tf32_rna((vs[7] + acc[7]) * inv_d);
    *(float4*)op = o1;
    *(float4*)(op + 4) = o2;
}

// ---------------------------------------------------------------------------
extern "C" void kernel_launch(void* const* d_in, const int* in_sizes, int n_in,
                              void* d_out, int out_size) {
    const float* x  = (const float*)d_in[0];
    const int*   ei = (const int*)d_in[1];     // int32 (JAX x64 disabled)
    const float* Wq = (const float*)d_in[2];
    const float* Wk = (const float*)d_in[3];
    const float* Wv = (const float*)d_in[4];
    const float* Wo = (const float*)d_in[5];
    const float* bo = (const float*)d_in[6];
    float*       out = (float*)d_out;

    cudaFuncSetAttribute(gemm_qkv_kernel,
                         cudaFuncAttributeMaxDynamicSharedMemorySize, QKV_SMEM_BYTES);
    cudaFuncSetAttribute(gemm_out_kernel,
                         cudaFuncAttributeMaxDynamicSharedMemorySize, SMEM2_BYTES);

    zero_small_kernel<<<17, 256>>>();
    bucket_kernel<<<Ee / 256, 256>>>(ei);
    permute_kernel<<<512, 256>>>(x, Wq, Wk, Wv, Wo);
    gemm_qkv_kernel<<<dim3(2, 64, 3), 128, QKV_SMEM_BYTES>>>();
    vsum_kernel<<<Nn / 16, 256>>>();
    row_kernel<<<Nn / 8, 256>>>();
    gemm_out_kernel<<<dim3(Dd / 128, Nn / 64, 1), 256, SMEM2_BYTES>>>(bo, out);
}